// round 2
// baseline (speedup 1.0000x reference)
#include <cuda_runtime.h>
#include <float.h>

#define BB 4096
#define NN 2048
#define THREADS 512   // 512 threads * 4 floats = 2048 = exactly one row per tensor

// Scratch: per-row weighted loss. Deterministic (fixed-order final sum).
__device__ float g_partials[BB];
__device__ unsigned int g_count = 0;

__global__ __launch_bounds__(THREADS)
void wnrmse_fused_kernel(const float* __restrict__ o1, const float* __restrict__ t1,
                         const float* __restrict__ o2, const float* __restrict__ t2,
                         const float* __restrict__ o3, const float* __restrict__ t3,
                         float* __restrict__ out) {
    const int b   = blockIdx.x;
    const int tid = threadIdx.x;
    const size_t off = (size_t)b * (NN / 4) + tid;   // float4 index into the row

    // Front-batch all 6 loads (MLP_p1 = 6, all 128B-coalesced).
    const float4 a1 = reinterpret_cast<const float4*>(o1)[off];
    const float4 b1 = reinterpret_cast<const float4*>(t1)[off];
    const float4 a2 = reinterpret_cast<const float4*>(o2)[off];
    const float4 b2 = reinterpret_cast<const float4*>(t2)[off];
    const float4 a3 = reinterpret_cast<const float4*>(o3)[off];
    const float4 b3 = reinterpret_cast<const float4*>(t3)[off];

    float ssq1 = 0.f, ssq2 = 0.f, ssq3 = 0.f;
    float mx1 = -FLT_MAX, mx2 = -FLT_MAX, mx3 = -FLT_MAX;
    float mn1 =  FLT_MAX, mn2 =  FLT_MAX, mn3 =  FLT_MAX;

    {
        float d;
        d = a1.x - b1.x; ssq1 = fmaf(d, d, ssq1); mx1 = fmaxf(mx1, b1.x); mn1 = fminf(mn1, b1.x);
        d = a1.y - b1.y; ssq1 = fmaf(d, d, ssq1); mx1 = fmaxf(mx1, b1.y); mn1 = fminf(mn1, b1.y);
        d = a1.z - b1.z; ssq1 = fmaf(d, d, ssq1); mx1 = fmaxf(mx1, b1.z); mn1 = fminf(mn1, b1.z);
        d = a1.w - b1.w; ssq1 = fmaf(d, d, ssq1); mx1 = fmaxf(mx1, b1.w); mn1 = fminf(mn1, b1.w);

        d = a2.x - b2.x; ssq2 = fmaf(d, d, ssq2); mx2 = fmaxf(mx2, b2.x); mn2 = fminf(mn2, b2.x);
        d = a2.y - b2.y; ssq2 = fmaf(d, d, ssq2); mx2 = fmaxf(mx2, b2.y); mn2 = fminf(mn2, b2.y);
        d = a2.z - b2.z; ssq2 = fmaf(d, d, ssq2); mx2 = fmaxf(mx2, b2.z); mn2 = fminf(mn2, b2.z);
        d = a2.w - b2.w; ssq2 = fmaf(d, d, ssq2); mx2 = fmaxf(mx2, b2.w); mn2 = fminf(mn2, b2.w);

        d = a3.x - b3.x; ssq3 = fmaf(d, d, ssq3); mx3 = fmaxf(mx3, b3.x); mn3 = fminf(mn3, b3.x);
        d = a3.y - b3.y; ssq3 = fmaf(d, d, ssq3); mx3 = fmaxf(mx3, b3.y); mn3 = fminf(mn3, b3.y);
        d = a3.z - b3.z; ssq3 = fmaf(d, d, ssq3); mx3 = fmaxf(mx3, b3.z); mn3 = fminf(mn3, b3.z);
        d = a3.w - b3.w; ssq3 = fmaf(d, d, ssq3); mx3 = fmaxf(mx3, b3.w); mn3 = fminf(mn3, b3.w);
    }

    // Intra-warp reduce (9 values)
    #pragma unroll
    for (int s = 16; s > 0; s >>= 1) {
        ssq1 += __shfl_xor_sync(0xFFFFFFFFu, ssq1, s);
        ssq2 += __shfl_xor_sync(0xFFFFFFFFu, ssq2, s);
        ssq3 += __shfl_xor_sync(0xFFFFFFFFu, ssq3, s);
        mx1 = fmaxf(mx1, __shfl_xor_sync(0xFFFFFFFFu, mx1, s));
        mx2 = fmaxf(mx2, __shfl_xor_sync(0xFFFFFFFFu, mx2, s));
        mx3 = fmaxf(mx3, __shfl_xor_sync(0xFFFFFFFFu, mx3, s));
        mn1 = fminf(mn1, __shfl_xor_sync(0xFFFFFFFFu, mn1, s));
        mn2 = fminf(mn2, __shfl_xor_sync(0xFFFFFFFFu, mn2, s));
        mn3 = fminf(mn3, __shfl_xor_sync(0xFFFFFFFFu, mn3, s));
    }

    // Cross-warp reduce (16 warps)
    __shared__ float sm[9][16];
    const int w = tid >> 5, l = tid & 31;
    if (l == 0) {
        sm[0][w] = ssq1; sm[1][w] = ssq2; sm[2][w] = ssq3;
        sm[3][w] = mx1;  sm[4][w] = mx2;  sm[5][w] = mx3;
        sm[6][w] = mn1;  sm[7][w] = mn2;  sm[8][w] = mn3;
    }
    __syncthreads();

    if (w == 0) {
        float v0 = (l < 16) ? sm[0][l] : 0.f;
        float v1 = (l < 16) ? sm[1][l] : 0.f;
        float v2 = (l < 16) ? sm[2][l] : 0.f;
        float v3 = (l < 16) ? sm[3][l] : -FLT_MAX;
        float v4 = (l < 16) ? sm[4][l] : -FLT_MAX;
        float v5 = (l < 16) ? sm[5][l] : -FLT_MAX;
        float v6 = (l < 16) ? sm[6][l] :  FLT_MAX;
        float v7 = (l < 16) ? sm[7][l] :  FLT_MAX;
        float v8 = (l < 16) ? sm[8][l] :  FLT_MAX;
        #pragma unroll
        for (int s = 8; s > 0; s >>= 1) {
            v0 += __shfl_xor_sync(0xFFFFFFFFu, v0, s);
            v1 += __shfl_xor_sync(0xFFFFFFFFu, v1, s);
            v2 += __shfl_xor_sync(0xFFFFFFFFu, v2, s);
            v3 = fmaxf(v3, __shfl_xor_sync(0xFFFFFFFFu, v3, s));
            v4 = fmaxf(v4, __shfl_xor_sync(0xFFFFFFFFu, v4, s));
            v5 = fmaxf(v5, __shfl_xor_sync(0xFFFFFFFFu, v5, s));
            v6 = fminf(v6, __shfl_xor_sync(0xFFFFFFFFu, v6, s));
            v7 = fminf(v7, __shfl_xor_sync(0xFFFFFFFFu, v7, s));
            v8 = fminf(v8, __shfl_xor_sync(0xFFFFFFFFu, v8, s));
        }
        if (l == 0) {
            const float inv_n = 1.0f / NN;
            float loss = 0.50f * sqrtf(v0 * inv_n) / (v3 - v6)
                       + 0.25f * sqrtf(v1 * inv_n) / (v4 - v7)
                       + 0.25f * sqrtf(v2 * inv_n) / (v5 - v8);
            g_partials[b] = loss;
            __threadfence();
        }
    }
    __syncthreads();

    // Last block performs the final (fixed-order, deterministic) reduction.
    __shared__ unsigned int s_ticket;
    if (tid == 0) s_ticket = atomicAdd(&g_count, 1u);
    __syncthreads();

    if (s_ticket == (unsigned)(gridDim.x - 1)) {
        float s = 0.f;
        #pragma unroll
        for (int i = tid; i < BB; i += THREADS) s += g_partials[i];

        #pragma unroll
        for (int sh = 16; sh > 0; sh >>= 1)
            s += __shfl_xor_sync(0xFFFFFFFFu, s, sh);

        __shared__ float s_fin[16];
        if (l == 0) s_fin[w] = s;
        __syncthreads();
        if (w == 0) {
            float a = (l < 16) ? s_fin[l] : 0.f;
            #pragma unroll
            for (int sh = 8; sh > 0; sh >>= 1)
                a += __shfl_xor_sync(0xFFFFFFFFu, a, sh);
            if (l == 0) {
                out[0] = a * (1.0f / BB);
                g_count = 0;   // reset for next graph replay
            }
        }
    }
}

extern "C" void kernel_launch(void* const* d_in, const int* in_sizes, int n_in,
                              void* d_out, int out_size) {
    const float* o1 = (const float*)d_in[0];
    const float* t1 = (const float*)d_in[1];
    const float* o2 = (const float*)d_in[2];
    const float* t2 = (const float*)d_in[3];
    const float* o3 = (const float*)d_in[4];
    const float* t3 = (const float*)d_in[5];
    float* out = (float*)d_out;

    wnrmse_fused_kernel<<<BB, THREADS>>>(o1, t1, o2, t2, o3, t3, out);
}